// round 3
// baseline (speedup 1.0000x reference)
#include <cuda_runtime.h>
#include <cuda_fp16.h>
#include <math.h>

// Problem constants
#define Bz   64
#define Lz   512
#define Dz   256
#define Hz   256
#define GRID 128
#define NTH  256

// -------- device scratch (static; no allocations allowed) --------
__device__ float  g_P[Lz * Bz * Hz];      // 32 MB: P[l][b][j] = x@Wx^T + bx + bh; later overwritten with listH
__device__ __half g_enc[Lz * Bz * Hz];    // 16 MB: enc[l][b][j] in fp16
__device__ float  g_WhT[Hz * Hz];         // WhT[k][j] = Wh[j][k]
__device__ float  g_hf[Bz * Hz];
__device__ float  g_hb[Bz * Hz];
__device__ float  g_ctx[Bz * Hz];
__device__ float  g_epart[4 * Lz];        // energy partials [ig][l]
__device__ unsigned long long g_cnt = 0;  // monotonic barrier counters (persist across replays)
__device__ unsigned long long g_rel = 0;

// -------- grid-wide barrier (monotonic generations; all CTAs resident) --------
__device__ __forceinline__ void gbar() {
    __syncthreads();
    if (threadIdx.x == 0) {
        __threadfence();
        unsigned long long a = atomicAdd(&g_cnt, 1ULL) + 1ULL;
        unsigned long long target = (a + (unsigned long long)GRID - 1ULL) / (unsigned long long)GRID;
        if ((a % (unsigned long long)GRID) == 0ULL) {
            atomicAdd(&g_rel, 1ULL);
        }
        while (*((volatile unsigned long long*)&g_rel) < target) { }
        __threadfence();
    }
    __syncthreads();
}

// -------- kernel 1: transpose Wh --------
__global__ void k_pre(const float* __restrict__ Wh) {
    int t = blockIdx.x * 256 + threadIdx.x;
    if (t < Hz * Hz) {
        int j = t >> 8, k = t & 255;
        g_WhT[k * 256 + j] = Wh[j * 256 + k];
    }
}

// -------- kernel 2: P[l][b][j] = sum_k x[b][l][k]*Wx[j][k] + bx[j] + bh[j] --------
// GEMM: M rows m = l*64+b (block of 64 rows = one l, all b), N=256 cols, K=256.
__global__ void k_gemm(const float* __restrict__ x, const float* __restrict__ Wx,
                       const float* __restrict__ bx, const float* __restrict__ bh) {
    __shared__ float As[32][65];
    __shared__ float Bs[32][65];
    const int bm = blockIdx.y;       // l index (0..511)
    const int bn = blockIdx.x;       // col block (0..3)
    const int tid = threadIdx.x;
    const int ty = tid >> 4, tx = tid & 15;

    float acc[4][4];
#pragma unroll
    for (int i = 0; i < 4; i++)
#pragma unroll
        for (int j = 0; j < 4; j++) acc[i][j] = 0.f;

    for (int kt = 0; kt < 256; kt += 32) {
#pragma unroll
        for (int i = 0; i < 8; i++) {
            int lin = tid + i * 256;         // 0..2047
            int mm = lin >> 5, kk = lin & 31;
            // row m = bm*64+mm -> l=bm, b=mm ; x row base = (b*512 + l)*256
            As[kk][mm] = x[(mm * 512 + bm) * 256 + kt + kk];
            Bs[kk][mm] = Wx[(bn * 64 + mm) * 256 + kt + kk];
        }
        __syncthreads();
#pragma unroll
        for (int kk = 0; kk < 32; kk++) {
            float a[4], bb[4];
#pragma unroll
            for (int i = 0; i < 4; i++) a[i] = As[kk][ty * 4 + i];
#pragma unroll
            for (int j = 0; j < 4; j++) bb[j] = Bs[kk][tx * 4 + j];
#pragma unroll
            for (int i = 0; i < 4; i++)
#pragma unroll
                for (int j = 0; j < 4; j++) acc[i][j] += a[i] * bb[j];
        }
        __syncthreads();
    }
#pragma unroll
    for (int i = 0; i < 4; i++) {
        int m = bm * 64 + ty * 4 + i;
#pragma unroll
        for (int j = 0; j < 4; j++) {
            int jj = bn * 64 + tx * 4 + j;
            g_P[m * 256 + jj] = acc[i][j] + bx[jj] + bh[jj];
        }
    }
}

// -------- kernel 3: persistent scan kernel (fwd+bwd scans, then attention scan) --------
__global__ void __launch_bounds__(NTH, 1) k_scan() {
    __shared__ float sA[256], sB[256], sC[256], sD[256];
    __shared__ float sAl[512];
    __shared__ float sS[40];

    const int cta = blockIdx.x;
    const int tid = threadIdx.x;
    const int b   = cta >> 1;        // batch element
    const int jh  = cta & 1;         // column half
    const int jl  = tid & 127;
    const int kh  = tid >> 7;        // k half (0/1)
    const int j   = jh * 128 + jl;
    const int lane = tid & 31, wid = tid >> 5;

    // init state
    if (cta < 64) {
        int idx = cta * 256 + tid;
        g_hf[idx] = 0.f;
        g_hb[idx] = 0.f;
    }
    float cf = 0.f, cb = 0.f;
    gbar();

    // ---------------- Phase A: forward + backward scans fused ----------------
    for (int s = 0; s < Lz; s++) {
        sA[tid] = g_hf[b * 256 + tid];
        sB[tid] = g_hb[b * 256 + tid];
        __syncthreads();
        float af = 0.f, ab = 0.f;
        const int kb = kh * 128;
        const float* wp = g_WhT + kb * 256 + j;
#pragma unroll 8
        for (int k = 0; k < 128; k++) {
            float w = wp[k * 256];
            af += sA[kb + k] * w;
            ab += sB[kb + k] * w;
        }
        sC[tid] = af;
        sD[tid] = ab;
        __syncthreads();
        float hn;
        if (kh == 0) {
            float pre = sC[jl] + sC[128 + jl] + g_P[s * 16384 + b * 256 + j];
            float sg = 1.f / (1.f + expf(-pre));
            float gg = tanhf(pre);
            cf = sg * (cf + gg);
            hn = sg * tanhf(cf);
            g_hf[b * 256 + j] = hn;
        } else {
            float pre = sD[jl] + sD[128 + jl] + g_P[(Lz - 1 - s) * 16384 + b * 256 + j];
            float sg = 1.f / (1.f + expf(-pre));
            float gg = tanhf(pre);
            cb = sg * (cb + gg);
            hn = sg * tanhf(cb);
            g_hb[b * 256 + j] = hn;
        }
        __syncthreads();
        if (kh == 0) sC[jl] = hn; else sD[jl] = hn;
        __syncthreads();
        if (kh == 0) {
            g_enc[s * 16384 + b * 256 + j] = __float2half(0.5f * (sC[jl] + sD[jl]));
        }
        gbar();
    }

    // ---------------- Phase B: attention scan ----------------
    // 2D shard: lg in [0,32) owns 16 l-values, ig in [0,4) owns 4096 (b,h) indices
    const int lg = cta >> 2, ig = cta & 3;
    const int l0 = lg * 16;
    const int idx0 = ig * 4096;

    for (int t = 0; t < Lz; t++) {
        // ---- energies partials (also re-init ctx := h via lg==0 CTAs) ----
        float e[16];
#pragma unroll
        for (int i = 0; i < 16; i++) e[i] = 0.f;
        for (int it = 0; it < 16; it++) {
            int idx = idx0 + it * 256 + tid;
            float hv = g_hb[idx];
            if (lg == 0) g_ctx[idx] = hv;
            const __half* ep = g_enc + (size_t)l0 * 16384 + idx;
#pragma unroll
            for (int i = 0; i < 16; i++)
                e[i] += hv * __half2float(ep[(size_t)i * 16384]);
        }
#pragma unroll
        for (int i = 0; i < 16; i++) {
            for (int o = 16; o > 0; o >>= 1) e[i] += __shfl_down_sync(0xffffffffu, e[i], o);
        }
        if (lane == 0) {
#pragma unroll
            for (int i = 0; i < 16; i++) sC[wid * 16 + i] = e[i];
        }
        __syncthreads();
        if (tid < 16) {
            float ssum = 0.f;
#pragma unroll
            for (int w = 0; w < 8; w++) ssum += sC[w * 16 + tid];
            g_epart[ig * 512 + l0 + tid] = ssum;
        }
        gbar();  // barrier A

        // ---- softmax over 512 energies (redundant per CTA, deterministic) ----
        int la = tid, lb2 = tid + 256;
        float e0 = g_epart[la] + g_epart[512 + la] + g_epart[1024 + la] + g_epart[1536 + la];
        float e1 = g_epart[lb2] + g_epart[512 + lb2] + g_epart[1024 + lb2] + g_epart[1536 + lb2];
        float m = fmaxf(e0, e1);
        for (int o = 16; o > 0; o >>= 1) m = fmaxf(m, __shfl_xor_sync(0xffffffffu, m, o));
        if (lane == 0) sS[wid] = m;
        __syncthreads();
        if (tid == 0) {
            float mm = sS[0];
            for (int w = 1; w < 8; w++) mm = fmaxf(mm, sS[w]);
            sS[32] = mm;
        }
        __syncthreads();
        float M = sS[32];
        float x0 = expf(e0 - M), x1 = expf(e1 - M);
        float ps = x0 + x1;
        for (int o = 16; o > 0; o >>= 1) ps += __shfl_xor_sync(0xffffffffu, ps, o);
        if (lane == 0) sS[wid] = ps;
        __syncthreads();
        if (tid == 0) {
            float ss = 0.f;
            for (int w = 0; w < 8; w++) ss += sS[w];
            sS[33] = 1.f / ss;
        }
        __syncthreads();
        float inv = sS[33];
        sAl[tid]       = x0 * inv;
        sAl[tid + 256] = x1 * inv;
        __syncthreads();

        // ---- context: ctx[idx] += sum_l alpha[l]*enc[l][idx] over this CTA's 16 l ----
        for (int it = 0; it < 16; it++) {
            int idx = idx0 + it * 256 + tid;
            const __half* ep = g_enc + (size_t)l0 * 16384 + idx;
            float acc = 0.f;
#pragma unroll
            for (int i = 0; i < 16; i++)
                acc += sAl[l0 + i] * __half2float(ep[(size_t)i * 16384]);
            atomicAdd(&g_ctx[idx], acc);
        }
        gbar();  // barrier B

        // ---- cell: pre = ctx@WhT + P[t]; update (h,c); listH -> overwrite P[t] ----
        sA[tid] = g_ctx[b * 256 + tid];
        __syncthreads();
        float a = 0.f;
        const int kb = kh * 128;
        const float* wp = g_WhT + kb * 256 + j;
#pragma unroll 8
        for (int k = 0; k < 128; k++) a += sA[kb + k] * wp[k * 256];
        sC[tid] = a;
        __syncthreads();
        if (kh == 1) {
            float pre = sC[jl] + sC[128 + jl] + g_P[t * 16384 + b * 256 + j];
            float sg = 1.f / (1.f + expf(-pre));
            float gg = tanhf(pre);
            cb = sg * (cb + gg);
            float hn = sg * tanhf(cb);
            g_hb[b * 256 + j] = hn;
            g_P[t * 16384 + b * 256 + j] = hn;   // listH[t][b][j]
        }
        gbar();  // barrier C
    }
}

// -------- kernel 4: out = listH@Wl^T + bl, mask, flatten [B,L,2] --------
__global__ void k_proj(const float* __restrict__ Wl, const float* __restrict__ bl,
                       const int* __restrict__ slen, float* __restrict__ out) {
    int warp = blockIdx.x * (blockDim.x >> 5) + (threadIdx.x >> 5);
    int lane = threadIdx.x & 31;
    if (warp >= Bz * Lz) return;
    int b = warp >> 9, l = warp & 511;
    const float* hrow = g_P + ((size_t)l * 16384 + b * 256);
    float a0 = 0.f, a1 = 0.f;
#pragma unroll
    for (int i = 0; i < 8; i++) {
        float h = hrow[lane + 32 * i];
        a0 += h * Wl[lane + 32 * i];
        a1 += h * Wl[256 + lane + 32 * i];
    }
    for (int o = 16; o > 0; o >>= 1) {
        a0 += __shfl_down_sync(0xffffffffu, a0, o);
        a1 += __shfl_down_sync(0xffffffffu, a1, o);
    }
    if (lane == 0) {
        float o0 = a0 + bl[0];
        float o1 = a1 + bl[1];
        if (l > slen[b]) { o0 = 0.f; o1 = 1.f; }
        out[(size_t)warp * 2]     = o0;
        out[(size_t)warp * 2 + 1] = o1;
    }
}

// -------- host launcher --------
extern "C" void kernel_launch(void* const* d_in, const int* in_sizes, int n_in,
                              void* d_out, int out_size) {
    const float* x    = (const float*)d_in[0];
    const int*   slen = (const int*)  d_in[1];
    const float* Wh   = (const float*)d_in[2];
    const float* bh   = (const float*)d_in[3];
    const float* Wx   = (const float*)d_in[4];
    const float* bx   = (const float*)d_in[5];
    const float* Wl   = (const float*)d_in[6];
    const float* bl   = (const float*)d_in[7];
    float* out = (float*)d_out;

    k_pre<<<256, 256>>>(Wh);
    k_gemm<<<dim3(4, 512), 256>>>(x, Wx, bx, bh);
    k_scan<<<GRID, NTH>>>();
    k_proj<<<4096, 256>>>(Wl, bl, slen, out);
}

// round 4
// speedup vs baseline: 1.3263x; 1.3263x over previous
#include <cuda_runtime.h>
#include <cuda_fp16.h>
#include <math.h>

// Problem constants
#define Bz   64
#define Lz   512
#define Hz   256
#define GRID 64
#define NTH  512

// SMEM-resident weight rows [0, KS_SMEM); rest streamed from L2
#define KS_SMEM 192

// -------- device scratch --------
__device__ float  g_P[Lz * Bz * Hz];      // P[(l*64+b)*256+j]; later overwritten with listH
__device__ __half g_enc[Lz * Bz * Hz];    // enc[(l*64+b)*256+j]
__device__ float  g_WhT[Hz * Hz];         // WhT[k*256+j] = Wh[j][k]
__device__ float  g_e3[3][Lz];            // rotating energy buffers
__device__ unsigned long long g_cnt = 0;  // monotonic barrier counters
__device__ unsigned long long g_rel = 0;

// -------- grid barrier (64 resident CTAs; monotonic generations) --------
__device__ __forceinline__ void gbar() {
    __threadfence();              // release (orders my stores; gpu-scope)
    __syncthreads();
    if (threadIdx.x == 0) {
        unsigned long long a = atomicAdd(&g_cnt, 1ULL) + 1ULL;
        unsigned long long target = (a + (unsigned long long)GRID - 1ULL) / (unsigned long long)GRID;
        if ((a % (unsigned long long)GRID) == 0ULL) atomicAdd(&g_rel, 1ULL);
        while (*((volatile unsigned long long*)&g_rel) < target) { }
    }
    __syncthreads();
    __threadfence();              // acquire (CCTL.IVALL -> fresh L1 for global reads)
}

// -------- kernel 1: transpose Wh --------
__global__ void k_pre(const float* __restrict__ Wh) {
    int t = blockIdx.x * 256 + threadIdx.x;
    if (t < Hz * Hz) {
        int j = t >> 8, k = t & 255;
        g_WhT[k * 256 + j] = Wh[j * 256 + k];
    }
}

// -------- kernel 2: P[(l*64+b)*256+j] = x@Wx^T + bx + bh --------
__global__ void k_gemm(const float* __restrict__ x, const float* __restrict__ Wx,
                       const float* __restrict__ bx, const float* __restrict__ bh) {
    __shared__ float As[32][65];
    __shared__ float Bs[32][65];
    const int bm = blockIdx.y;       // l
    const int bn = blockIdx.x;       // col block
    const int tid = threadIdx.x;
    const int ty = tid >> 4, tx = tid & 15;

    float acc[4][4];
#pragma unroll
    for (int i = 0; i < 4; i++)
#pragma unroll
        for (int j = 0; j < 4; j++) acc[i][j] = 0.f;

    for (int kt = 0; kt < 256; kt += 32) {
#pragma unroll
        for (int i = 0; i < 8; i++) {
            int lin = tid + i * 256;
            int mm = lin >> 5, kk = lin & 31;
            As[kk][mm] = x[(mm * 512 + bm) * 256 + kt + kk];
            Bs[kk][mm] = Wx[(bn * 64 + mm) * 256 + kt + kk];
        }
        __syncthreads();
#pragma unroll
        for (int kk = 0; kk < 32; kk++) {
            float a[4], bb[4];
#pragma unroll
            for (int i = 0; i < 4; i++) a[i] = As[kk][ty * 4 + i];
#pragma unroll
            for (int j = 0; j < 4; j++) bb[j] = Bs[kk][tx * 4 + j];
#pragma unroll
            for (int i = 0; i < 4; i++)
#pragma unroll
                for (int j = 0; j < 4; j++) acc[i][j] += a[i] * bb[j];
        }
        __syncthreads();
    }
#pragma unroll
    for (int i = 0; i < 4; i++) {
        int m = bm * 64 + ty * 4 + i;
#pragma unroll
        for (int j = 0; j < 4; j++) {
            int jj = bn * 64 + tx * 4 + j;
            g_P[m * 256 + jj] = acc[i][j] + bx[jj] + bh[jj];
        }
    }
}

// -------- kernel 3: persistent per-batch scan kernel --------
// CTA = b. 512 threads: (kh = t>>8, j = t&255).
// kh==0 covers k in [0,96) smem + [192,224) gmem; kh==1 covers [96,192) smem + [224,256) gmem.
__global__ void __launch_bounds__(NTH, 1) k_scan() {
    extern __shared__ float smem[];
    float* wS   = smem;                 // 49152 floats (192KB): WhT rows 0..191
    float* sHf  = smem + 49152;         // 256
    float* sHb  = sHf + 256;            // 256
    float* sRed = sHb + 256;            // 1024
    float* sCtx = sRed + 1024;          // 256
    float* sAl  = sCtx + 256;           // 512
    float* sPre = sAl + 512;            // 512
    float* sSm  = sPre + 512;           // 32

    const int b   = blockIdx.x;
    const int tid = threadIdx.x;
    const int kh  = tid >> 8;
    const int j   = tid & 255;
    const int ks0 = kh ? 96 : 0;        // smem k-range start (96 rows)
    const int kg0 = kh ? 224 : 192;     // gmem k-range start (32 rows)

    // prologue: load weights into smem, zero state
    for (int i = tid; i < KS_SMEM * 256; i += NTH) wS[i] = g_WhT[i];
    if (tid < 256) { sHf[tid] = 0.f; sHb[tid] = 0.f; }
    if (b == 0) g_e3[0][tid] = 0.f;
    __syncthreads();

    float cst = 0.f;   // cell state: cf for kh==0 threads, cb for kh==1 threads

    // ---------------- Phase A: fwd + bwd scans (no grid barriers) ----------------
    for (int s = 0; s < Lz; s++) {
        float af = 0.f, ab = 0.f;
        {
            const float4* hf4 = (const float4*)(sHf + ks0);
            const float4* hb4 = (const float4*)(sHb + ks0);
            const float* wp = wS + ks0 * 256 + j;
#pragma unroll 4
            for (int q = 0; q < 24; q++) {
                float4 hf = hf4[q], hb = hb4[q];
                const float* w4 = wp + q * 1024;
                float w0 = w4[0], w1 = w4[256], w2 = w4[512], w3 = w4[768];
                af += hf.x * w0 + hf.y * w1 + hf.z * w2 + hf.w * w3;
                ab += hb.x * w0 + hb.y * w1 + hb.z * w2 + hb.w * w3;
            }
        }
        {
            const float4* hf4 = (const float4*)(sHf + kg0);
            const float4* hb4 = (const float4*)(sHb + kg0);
            const float* wp = g_WhT + kg0 * 256 + j;
#pragma unroll
            for (int q = 0; q < 8; q++) {
                float4 hf = hf4[q], hb = hb4[q];
                const float* w4 = wp + q * 1024;
                float w0 = w4[0], w1 = w4[256], w2 = w4[512], w3 = w4[768];
                af += hf.x * w0 + hf.y * w1 + hf.z * w2 + hf.w * w3;
                ab += hb.x * w0 + hb.y * w1 + hb.z * w2 + hb.w * w3;
            }
        }
        sRed[kh * 256 + j]       = af;
        sRed[512 + kh * 256 + j] = ab;
        __syncthreads();
        if (kh == 0) {
            float pre = sRed[j] + sRed[256 + j] + g_P[((size_t)s * 64 + b) * 256 + j];
            float sg = 1.f / (1.f + expf(-pre));
            float gg = tanhf(pre);
            cst = sg * (cst + gg);
            sHf[j] = sg * tanhf(cst);
        } else {
            float pre = sRed[512 + j] + sRed[768 + j] + g_P[((size_t)(511 - s) * 64 + b) * 256 + j];
            float sg = 1.f / (1.f + expf(-pre));
            float gg = tanhf(pre);
            cst = sg * (cst + gg);
            sHb[j] = sg * tanhf(cst);
        }
        __syncthreads();
        if (kh == 0)
            g_enc[((size_t)s * 64 + b) * 256 + j] = __float2half(0.5f * (sHf[j] + sHb[j]));
    }

    gbar();   // phase boundary: g_e3[0] zero + enc visible (enc is CTA-local anyway)

    // ---------------- Phase B: attention scan (ONE grid barrier / step) ----------------
    // state: h in sHb, c in cst of kh==1 threads (continues backward-scan carry)
    for (int t = 0; t < Lz; t++) {
        const int bufc = t % 3, bufn = (t + 1) % 3;

        // ---- interval 1: energies. thread tid handles l = tid ----
        {
            const uint4* rp = (const uint4*)(g_enc + ((size_t)tid * 64 + b) * 256);
            const float4* h4 = (const float4*)sHb;
            float e = 0.f;
#pragma unroll 8
            for (int i = 0; i < 32; i++) {
                uint4 v = rp[i];
                float4 ha = h4[i * 2], hb = h4[i * 2 + 1];
                float2 f0 = __half22float2(*(__half2*)&v.x);
                float2 f1 = __half22float2(*(__half2*)&v.y);
                float2 f2 = __half22float2(*(__half2*)&v.z);
                float2 f3 = __half22float2(*(__half2*)&v.w);
                e += f0.x * ha.x + f0.y * ha.y + f1.x * ha.z + f1.y * ha.w
                   + f2.x * hb.x + f2.y * hb.y + f3.x * hb.z + f3.y * hb.w;
            }
            atomicAdd(&g_e3[bufc][tid], e);
            if (b == 0) g_e3[bufn][tid] = 0.f;   // prepare next buffer (race-free: 3-way rotation)
        }
        gbar();

        // ---- interval 2: softmax (replicated), context (local b), cell ----
        float myE = g_e3[bufc][tid];
        float m = myE;
#pragma unroll
        for (int o = 16; o > 0; o >>= 1) m = fmaxf(m, __shfl_xor_sync(0xffffffffu, m, o));
        if ((tid & 31) == 0) sSm[tid >> 5] = m;
        __syncthreads();
        if (tid == 0) {
            float mm = sSm[0];
#pragma unroll
            for (int w = 1; w < 16; w++) mm = fmaxf(mm, sSm[w]);
            sSm[16] = mm;
        }
        __syncthreads();
        float M = sSm[16];
        float ex = expf(myE - M);
        float ss = ex;
#pragma unroll
        for (int o = 16; o > 0; o >>= 1) ss += __shfl_xor_sync(0xffffffffu, ss, o);
        if ((tid & 31) == 0) sSm[tid >> 5] = ss;
        __syncthreads();
        if (tid == 0) {
            float tot = 0.f;
#pragma unroll
            for (int w = 0; w < 16; w++) tot += sSm[w];
            sSm[17] = 1.f / tot;
        }
        __syncthreads();
        sAl[tid] = ex * sSm[17];
        __syncthreads();

        // context partials: thread = (lq = tid>>7 in [0,4), jp = tid&127 -> j pair 2*jp)
        {
            const int jp = tid & 127, lq = tid >> 7;
            const __half2* bp = (const __half2*)g_enc;
            const float4* al4 = (const float4*)(sAl + lq * 128);
            float a0 = 0.f, a1 = 0.f;
#pragma unroll 4
            for (int q = 0; q < 32; q++) {
                float4 al = al4[q];
                int l = lq * 128 + q * 4;
                float2 f;
                f = __half22float2(bp[((size_t)(l + 0) * 64 + b) * 128 + jp]); a0 += al.x * f.x; a1 += al.x * f.y;
                f = __half22float2(bp[((size_t)(l + 1) * 64 + b) * 128 + jp]); a0 += al.y * f.x; a1 += al.y * f.y;
                f = __half22float2(bp[((size_t)(l + 2) * 64 + b) * 128 + jp]); a0 += al.z * f.x; a1 += al.z * f.y;
                f = __half22float2(bp[((size_t)(l + 3) * 64 + b) * 128 + jp]); a0 += al.w * f.x; a1 += al.w * f.y;
            }
            sRed[lq * 256 + jp * 2]     = a0;
            sRed[lq * 256 + jp * 2 + 1] = a1;
        }
        __syncthreads();
        if (tid < 256)
            sCtx[tid] = sHb[tid] + sRed[tid] + sRed[256 + tid] + sRed[512 + tid] + sRed[768 + tid];
        __syncthreads();

        // cell matvec: pre[j] = sum_k ctx[k]*WhT[k][j]
        {
            float a = 0.f;
            const float4* c4 = (const float4*)(sCtx + ks0);
            const float* wp = wS + ks0 * 256 + j;
#pragma unroll 4
            for (int q = 0; q < 24; q++) {
                float4 c = c4[q];
                const float* w4 = wp + q * 1024;
                a += c.x * w4[0] + c.y * w4[256] + c.z * w4[512] + c.w * w4[768];
            }
            const float4* cg = (const float4*)(sCtx + kg0);
            const float* gp = g_WhT + kg0 * 256 + j;
#pragma unroll
            for (int q = 0; q < 8; q++) {
                float4 c = cg[q];
                const float* w4 = gp + q * 1024;
                a += c.x * w4[0] + c.y * w4[256] + c.z * w4[512] + c.w * w4[768];
            }
            sPre[kh * 256 + j] = a;
        }
        __syncthreads();
        if (kh == 1) {
            float pre = sPre[j] + sPre[256 + j] + g_P[((size_t)t * 64 + b) * 256 + j];
            float sg = 1.f / (1.f + expf(-pre));
            float gg = tanhf(pre);
            cst = sg * (cst + gg);
            float hn = sg * tanhf(cst);
            sHb[j] = hn;
            g_P[((size_t)t * 64 + b) * 256 + j] = hn;   // listH
        }
        __syncthreads();
    }
}

// -------- kernel 4: out = listH@Wl^T + bl, mask --------
__global__ void k_proj(const float* __restrict__ Wl, const float* __restrict__ bl,
                       const int* __restrict__ slen, float* __restrict__ out) {
    int warp = blockIdx.x * (blockDim.x >> 5) + (threadIdx.x >> 5);
    int lane = threadIdx.x & 31;
    if (warp >= Bz * Lz) return;
    int b = warp >> 9, l = warp & 511;
    const float* hrow = g_P + ((size_t)l * 64 + b) * 256;
    float a0 = 0.f, a1 = 0.f;
#pragma unroll
    for (int i = 0; i < 8; i++) {
        float h = hrow[lane + 32 * i];
        a0 += h * Wl[lane + 32 * i];
        a1 += h * Wl[256 + lane + 32 * i];
    }
    for (int o = 16; o > 0; o >>= 1) {
        a0 += __shfl_down_sync(0xffffffffu, a0, o);
        a1 += __shfl_down_sync(0xffffffffu, a1, o);
    }
    if (lane == 0) {
        float o0 = a0 + bl[0];
        float o1 = a1 + bl[1];
        if (l > slen[b]) { o0 = 0.f; o1 = 1.f; }
        out[(size_t)warp * 2]     = o0;
        out[(size_t)warp * 2 + 1] = o1;
    }
}

// -------- host launcher --------
extern "C" void kernel_launch(void* const* d_in, const int* in_sizes, int n_in,
                              void* d_out, int out_size) {
    const float* x    = (const float*)d_in[0];
    const int*   slen = (const int*)  d_in[1];
    const float* Wh   = (const float*)d_in[2];
    const float* bh   = (const float*)d_in[3];
    const float* Wx   = (const float*)d_in[4];
    const float* bx   = (const float*)d_in[5];
    const float* Wl   = (const float*)d_in[6];
    const float* bl   = (const float*)d_in[7];
    float* out = (float*)d_out;

    const int smem_bytes = (49152 + 256 + 256 + 1024 + 256 + 512 + 512 + 32) * 4;
    cudaFuncSetAttribute(k_scan, cudaFuncAttributeMaxDynamicSharedMemorySize, smem_bytes);

    k_pre<<<256, 256>>>(Wh);
    k_gemm<<<dim3(4, 512), 256>>>(x, Wx, bx, bh);
    k_scan<<<GRID, NTH, smem_bytes>>>();
    k_proj<<<4096, 256>>>(Wl, bl, slen, out);
}

// round 5
// speedup vs baseline: 2.1278x; 1.6043x over previous
#include <cuda_runtime.h>
#include <cuda_fp16.h>
#include <math.h>

// Problem constants
#define Bz   64
#define Lz   512
#define Hz   256
#define GRID 64
#define NTH  512

// SMEM-resident weight rows [0, KS_SMEM); rest streamed from L2
#define KS_SMEM 192

// -------- device scratch --------
__device__ float  g_P[Lz * Bz * Hz];      // P[(l*64+b)*256+j]; later overwritten with listH
__device__ __half g_enc[Lz * Bz * Hz];    // enc[(l*64+b)*256+j]
__device__ float  g_WhT[Hz * Hz];         // WhT[k*256+j] = Wh[j][k]
__device__ float  g_e3[3][Lz];            // rotating energy buffers
__device__ unsigned long long g_cnt = 0;  // monotonic barrier counters
__device__ unsigned long long g_rel = 0;

// -------- grid barrier (64 resident CTAs; monotonic generations) --------
// Release: every thread fences once (orders its atomics/stores to gpu scope),
// thread0 arrives. Acquire: thread0 fence after spin; cross-CTA data is read
// with __ldcg (L2) so no full-CTA L1 invalidate is required.
__device__ __forceinline__ void gbar() {
    __threadfence();
    __syncthreads();
    if (threadIdx.x == 0) {
        unsigned long long a = atomicAdd(&g_cnt, 1ULL) + 1ULL;
        unsigned long long target = (a + (unsigned long long)GRID - 1ULL) / (unsigned long long)GRID;
        if ((a % (unsigned long long)GRID) == 0ULL) atomicAdd(&g_rel, 1ULL);
        while (*((volatile unsigned long long*)&g_rel) < target) { }
        __threadfence();
    }
    __syncthreads();
}

// -------- kernel 1: transpose Wh --------
__global__ void k_pre(const float* __restrict__ Wh) {
    int t = blockIdx.x * 256 + threadIdx.x;
    if (t < Hz * Hz) {
        int j = t >> 8, k = t & 255;
        g_WhT[k * 256 + j] = Wh[j * 256 + k];
    }
}

// -------- kernel 2: P[(l*64+b)*256+j] = x@Wx^T + bx + bh --------
__global__ void k_gemm(const float* __restrict__ x, const float* __restrict__ Wx,
                       const float* __restrict__ bx, const float* __restrict__ bh) {
    __shared__ float As[32][65];
    __shared__ float Bs[32][65];
    const int bm = blockIdx.y;
    const int bn = blockIdx.x;
    const int tid = threadIdx.x;
    const int ty = tid >> 4, tx = tid & 15;

    float acc[4][4];
#pragma unroll
    for (int i = 0; i < 4; i++)
#pragma unroll
        for (int j = 0; j < 4; j++) acc[i][j] = 0.f;

    for (int kt = 0; kt < 256; kt += 32) {
#pragma unroll
        for (int i = 0; i < 8; i++) {
            int lin = tid + i * 256;
            int mm = lin >> 5, kk = lin & 31;
            As[kk][mm] = x[(mm * 512 + bm) * 256 + kt + kk];
            Bs[kk][mm] = Wx[(bn * 64 + mm) * 256 + kt + kk];
        }
        __syncthreads();
#pragma unroll
        for (int kk = 0; kk < 32; kk++) {
            float a[4], bb[4];
#pragma unroll
            for (int i = 0; i < 4; i++) a[i] = As[kk][ty * 4 + i];
#pragma unroll
            for (int j = 0; j < 4; j++) bb[j] = Bs[kk][tx * 4 + j];
#pragma unroll
            for (int i = 0; i < 4; i++)
#pragma unroll
                for (int j = 0; j < 4; j++) acc[i][j] += a[i] * bb[j];
        }
        __syncthreads();
    }
#pragma unroll
    for (int i = 0; i < 4; i++) {
        int m = bm * 64 + ty * 4 + i;
#pragma unroll
        for (int j = 0; j < 4; j++) {
            int jj = bn * 64 + tx * 4 + j;
            g_P[m * 256 + jj] = acc[i][j] + bx[jj] + bh[jj];
        }
    }
}

// -------- smem layout (float offsets) --------
#define OFF_W     0
#define OFF_HF    49152
#define OFF_HB    49408
#define OFF_CTX   49664
#define OFF_AL    49920
#define OFF_PRE   50432
#define OFF_E     50944
#define OFF_SM    51456
#define OFF_RED   51488        // 16*256 = 4096 floats (phase A uses first 1024)
#define SMEM_FLTS (OFF_RED + 4096)

// -------- kernel 3: persistent per-batch scan --------
__global__ void __launch_bounds__(NTH, 1) k_scan() {
    extern __shared__ float smem[];
    float* wS   = smem + OFF_W;
    float* sHf  = smem + OFF_HF;
    float* sHb  = smem + OFF_HB;
    float* sCtx = smem + OFF_CTX;
    float* sAl  = smem + OFF_AL;
    float* sPre = smem + OFF_PRE;
    float* sE   = smem + OFF_E;
    float* sSm  = smem + OFF_SM;
    float* sRed = smem + OFF_RED;

    const int b    = blockIdx.x;
    const int tid  = threadIdx.x;
    const int kh   = tid >> 8;
    const int j    = tid & 255;
    const int lane = tid & 31;
    const int w    = tid >> 5;          // warp id (0..15)
    const int ks0  = kh ? 96 : 0;       // smem k-range (96 rows)
    const int kg0  = kh ? 224 : 192;    // gmem k-range (32 rows)

    // prologue
    for (int i = tid; i < KS_SMEM * 256; i += NTH) wS[i] = g_WhT[i];
    if (tid < 256) { sHf[tid] = 0.f; sHb[tid] = 0.f; }
    if (b == 0) g_e3[0][tid] = 0.f;
    __syncthreads();

    float cst = 0.f;  // cf for kh==0 threads, cb for kh==1 threads

    // ---------------- Phase A: fwd + bwd scans (no grid barriers) ----------------
    for (int s = 0; s < Lz; s++) {
        float af = 0.f, ab = 0.f;
        {
            const float4* hf4 = (const float4*)(sHf + ks0);
            const float4* hb4 = (const float4*)(sHb + ks0);
            const float* wp = wS + ks0 * 256 + j;
#pragma unroll 4
            for (int q = 0; q < 24; q++) {
                float4 hf = hf4[q], hb = hb4[q];
                const float* w4 = wp + q * 1024;
                float w0 = w4[0], w1 = w4[256], w2 = w4[512], w3 = w4[768];
                af += hf.x * w0 + hf.y * w1 + hf.z * w2 + hf.w * w3;
                ab += hb.x * w0 + hb.y * w1 + hb.z * w2 + hb.w * w3;
            }
        }
        {
            const float4* hf4 = (const float4*)(sHf + kg0);
            const float4* hb4 = (const float4*)(sHb + kg0);
            const float* wp = g_WhT + kg0 * 256 + j;
#pragma unroll
            for (int q = 0; q < 8; q++) {
                float4 hf = hf4[q], hb = hb4[q];
                const float* w4 = wp + q * 1024;
                float w0 = w4[0], w1 = w4[256], w2 = w4[512], w3 = w4[768];
                af += hf.x * w0 + hf.y * w1 + hf.z * w2 + hf.w * w3;
                ab += hb.x * w0 + hb.y * w1 + hb.z * w2 + hb.w * w3;
            }
        }
        sRed[kh * 256 + j]       = af;
        sRed[512 + kh * 256 + j] = ab;
        __syncthreads();
        if (kh == 0) {
            float pre = sRed[j] + sRed[256 + j] + g_P[((size_t)s * 64 + b) * 256 + j];
            float sg = 1.f / (1.f + expf(-pre));
            float gg = tanhf(pre);
            cst = sg * (cst + gg);
            sHf[j] = sg * tanhf(cst);
        } else {
            float pre = sRed[512 + j] + sRed[768 + j] + g_P[((size_t)(511 - s) * 64 + b) * 256 + j];
            float sg = 1.f / (1.f + expf(-pre));
            float gg = tanhf(pre);
            cst = sg * (cst + gg);
            sHb[j] = sg * tanhf(cst);
        }
        __syncthreads();
        if (kh == 0)
            g_enc[((size_t)s * 64 + b) * 256 + j] = __float2half(0.5f * (sHf[j] + sHb[j]));
    }

    gbar();  // phase boundary

    // ---------------- Phase B: attention scan (one grid barrier / step) ----------------
    for (int t = 0; t < Lz; t++) {
        const int bufc = t % 3, bufn = (t + 1) % 3;

        // ---- interval 1: energies. warp w owns rows l = w*32 .. w*32+31 ----
        {
            // register-resident h slice: h[lane*8 .. lane*8+7]
            float4 hA = ((const float4*)sHb)[lane * 2];
            float4 hB = ((const float4*)sHb)[lane * 2 + 1];
            const __half* base = g_enc + (size_t)b * 256 + (size_t)lane * 8;
#pragma unroll 4
            for (int i = 0; i < 32; i++) {
                int l = w * 32 + i;
                uint4 v = *(const uint4*)(base + (size_t)l * 16384);
                float2 f0 = __half22float2(*(__half2*)&v.x);
                float2 f1 = __half22float2(*(__half2*)&v.y);
                float2 f2 = __half22float2(*(__half2*)&v.z);
                float2 f3 = __half22float2(*(__half2*)&v.w);
                float p = f0.x * hA.x + f0.y * hA.y + f1.x * hA.z + f1.y * hA.w
                        + f2.x * hB.x + f2.y * hB.y + f3.x * hB.z + f3.y * hB.w;
#pragma unroll
                for (int o = 16; o > 0; o >>= 1) p += __shfl_xor_sync(0xffffffffu, p, o);
                if (lane == 0) sE[l] = p;
            }
        }
        __syncthreads();
        atomicAdd(&g_e3[bufc][tid], sE[tid]);
        if (b == 0) g_e3[bufn][tid] = 0.f;   // race-free: 3-way rotation
        gbar();

        // ---- interval 2: softmax (replicated), context (local b), cell ----
        float myE = __ldcg(&g_e3[bufc][tid]);
        float m = myE;
#pragma unroll
        for (int o = 16; o > 0; o >>= 1) m = fmaxf(m, __shfl_xor_sync(0xffffffffu, m, o));
        if (lane == 0) sSm[w] = m;
        __syncthreads();
        if (tid == 0) {
            float mm = sSm[0];
#pragma unroll
            for (int ww = 1; ww < 16; ww++) mm = fmaxf(mm, sSm[ww]);
            sSm[16] = mm;
        }
        __syncthreads();
        float M = sSm[16];
        float ex = expf(myE - M);
        float ss = ex;
#pragma unroll
        for (int o = 16; o > 0; o >>= 1) ss += __shfl_xor_sync(0xffffffffu, ss, o);
        if (lane == 0) sSm[w] = ss;
        __syncthreads();
        if (tid == 0) {
            float tot = 0.f;
#pragma unroll
            for (int ww = 0; ww < 16; ww++) tot += sSm[ww];
            sSm[17] = 1.f / tot;
        }
        __syncthreads();
        sAl[tid] = ex * sSm[17];
        __syncthreads();

        // context partials: warp w owns rows l = w*32..+31; lane owns j-oct lane*8..+7
        {
            float a0 = 0.f, a1 = 0.f, a2 = 0.f, a3 = 0.f;
            float a4 = 0.f, a5 = 0.f, a6 = 0.f, a7 = 0.f;
            const __half* base = g_enc + (size_t)b * 256 + (size_t)lane * 8;
#pragma unroll 4
            for (int i = 0; i < 32; i++) {
                int l = w * 32 + i;
                float al = sAl[l];
                uint4 v = *(const uint4*)(base + (size_t)l * 16384);
                float2 f0 = __half22float2(*(__half2*)&v.x);
                float2 f1 = __half22float2(*(__half2*)&v.y);
                float2 f2 = __half22float2(*(__half2*)&v.z);
                float2 f3 = __half22float2(*(__half2*)&v.w);
                a0 += al * f0.x; a1 += al * f0.y; a2 += al * f1.x; a3 += al * f1.y;
                a4 += al * f2.x; a5 += al * f2.y; a6 += al * f3.x; a7 += al * f3.y;
            }
            float4* dst = (float4*)(sRed + w * 256 + lane * 8);
            dst[0] = make_float4(a0, a1, a2, a3);
            dst[1] = make_float4(a4, a5, a6, a7);
        }
        __syncthreads();
        if (tid < 256) {
            float s = sHb[tid];
#pragma unroll
            for (int ww = 0; ww < 16; ww++) s += sRed[ww * 256 + tid];
            sCtx[tid] = s;
        }
        __syncthreads();

        // cell matvec: pre[j] = sum_k ctx[k]*WhT[k][j]
        {
            float a = 0.f;
            const float4* c4 = (const float4*)(sCtx + ks0);
            const float* wp = wS + ks0 * 256 + j;
#pragma unroll 4
            for (int q = 0; q < 24; q++) {
                float4 c = c4[q];
                const float* w4 = wp + q * 1024;
                a += c.x * w4[0] + c.y * w4[256] + c.z * w4[512] + c.w * w4[768];
            }
            const float4* cg = (const float4*)(sCtx + kg0);
            const float* gp = g_WhT + kg0 * 256 + j;
#pragma unroll
            for (int q = 0; q < 8; q++) {
                float4 c = cg[q];
                const float* w4 = gp + q * 1024;
                a += c.x * w4[0] + c.y * w4[256] + c.z * w4[512] + c.w * w4[768];
            }
            sPre[kh * 256 + j] = a;
        }
        __syncthreads();
        if (kh == 1) {
            float pre = sPre[j] + sPre[256 + j] + g_P[((size_t)t * 64 + b) * 256 + j];
            float sg = 1.f / (1.f + expf(-pre));
            float gg = tanhf(pre);
            cst = sg * (cst + gg);
            float hn = sg * tanhf(cst);
            sHb[j] = hn;
            g_P[((size_t)t * 64 + b) * 256 + j] = hn;   // listH
        }
        __syncthreads();
    }
}

// -------- kernel 4: out = listH@Wl^T + bl, mask --------
__global__ void k_proj(const float* __restrict__ Wl, const float* __restrict__ bl,
                       const int* __restrict__ slen, float* __restrict__ out) {
    int warp = blockIdx.x * (blockDim.x >> 5) + (threadIdx.x >> 5);
    int lane = threadIdx.x & 31;
    if (warp >= Bz * Lz) return;
    int b = warp >> 9, l = warp & 511;
    const float* hrow = g_P + ((size_t)l * 64 + b) * 256;
    float a0 = 0.f, a1 = 0.f;
#pragma unroll
    for (int i = 0; i < 8; i++) {
        float h = hrow[lane + 32 * i];
        a0 += h * Wl[lane + 32 * i];
        a1 += h * Wl[256 + lane + 32 * i];
    }
    for (int o = 16; o > 0; o >>= 1) {
        a0 += __shfl_down_sync(0xffffffffu, a0, o);
        a1 += __shfl_down_sync(0xffffffffu, a1, o);
    }
    if (lane == 0) {
        float o0 = a0 + bl[0];
        float o1 = a1 + bl[1];
        if (l > slen[b]) { o0 = 0.f; o1 = 1.f; }
        out[(size_t)warp * 2]     = o0;
        out[(size_t)warp * 2 + 1] = o1;
    }
}

// -------- host launcher --------
extern "C" void kernel_launch(void* const* d_in, const int* in_sizes, int n_in,
                              void* d_out, int out_size) {
    const float* x    = (const float*)d_in[0];
    const int*   slen = (const int*)  d_in[1];
    const float* Wh   = (const float*)d_in[2];
    const float* bh   = (const float*)d_in[3];
    const float* Wx   = (const float*)d_in[4];
    const float* bx   = (const float*)d_in[5];
    const float* Wl   = (const float*)d_in[6];
    const float* bl   = (const float*)d_in[7];
    float* out = (float*)d_out;

    const int smem_bytes = SMEM_FLTS * 4;
    cudaFuncSetAttribute(k_scan, cudaFuncAttributeMaxDynamicSharedMemorySize, smem_bytes);

    k_pre<<<256, 256>>>(Wh);
    k_gemm<<<dim3(4, 512), 256>>>(x, Wx, bx, bh);
    k_scan<<<GRID, NTH, smem_bytes>>>();
    k_proj<<<4096, 256>>>(Wl, bl, slen, out);
}

// round 6
// speedup vs baseline: 2.5042x; 1.1769x over previous
#include <cuda_runtime.h>
#include <cuda_fp16.h>
#include <math.h>

// Problem constants
#define Bz   64
#define Lz   512
#define Hz   256
#define GRID 128
#define NTH  512

#define KS_SMEM 192          // phase A: fp32 weight rows in smem
#define WB_ROWS 80           // phase B: fp32 weight rows (of my 128) in smem
#define EPITCH  65           // enc smem pitch in 4-byte words (260 B rows)

// -------- device scratch --------
__device__ float  g_P[Lz * Bz * Hz];       // P / listH
__device__ __half g_enc[Lz * Bz * Hz];     // enc fp16
__device__ float  g_WhT[Hz * Hz];          // WhT[k*256+j]
__device__ float  g_e3p[3 * Lz * 32];      // energies, padded 128B stride per l, 3 bufs
__device__ float  g_p3[3 * Bz * Hz];       // pre-partial exchange, 3 bufs
__device__ float  g_hc[Bz * 512];          // [b][0:256]=h_bwd_final, [256:512]=c_bwd_final
__device__ unsigned long long g_cnt = 0;   // monotonic barrier counter

// -------- grid barrier: single counter, monotonic generations --------
__device__ __forceinline__ void gbar() {
    __threadfence();     // release each thread's global stores/atomics
    __syncthreads();
    if (threadIdx.x == 0) {
        unsigned long long a = atomicAdd(&g_cnt, 1ULL);      // old value
        unsigned long long target = (a / (unsigned long long)GRID + 1ULL) * (unsigned long long)GRID;
        while (*((volatile unsigned long long*)&g_cnt) < target) { }
        __threadfence();
    }
    __syncthreads();
}

// -------- kernel 1: transpose Wh --------
__global__ void k_pre(const float* __restrict__ Wh) {
    int t = blockIdx.x * 256 + threadIdx.x;
    if (t < Hz * Hz) {
        int j = t >> 8, k = t & 255;
        g_WhT[k * 256 + j] = Wh[j * 256 + k];
    }
}

// -------- kernel 2: P = x@Wx^T + bx + bh --------
__global__ void k_gemm(const float* __restrict__ x, const float* __restrict__ Wx,
                       const float* __restrict__ bx, const float* __restrict__ bh) {
    __shared__ float As[32][65];
    __shared__ float Bs[32][65];
    const int bm = blockIdx.y;
    const int bn = blockIdx.x;
    const int tid = threadIdx.x;
    const int ty = tid >> 4, tx = tid & 15;

    float acc[4][4];
#pragma unroll
    for (int i = 0; i < 4; i++)
#pragma unroll
        for (int j = 0; j < 4; j++) acc[i][j] = 0.f;

    for (int kt = 0; kt < 256; kt += 32) {
#pragma unroll
        for (int i = 0; i < 8; i++) {
            int lin = tid + i * 256;
            int mm = lin >> 5, kk = lin & 31;
            As[kk][mm] = x[(mm * 512 + bm) * 256 + kt + kk];
            Bs[kk][mm] = Wx[(bn * 64 + mm) * 256 + kt + kk];
        }
        __syncthreads();
#pragma unroll
        for (int kk = 0; kk < 32; kk++) {
            float a[4], bb[4];
#pragma unroll
            for (int i = 0; i < 4; i++) a[i] = As[kk][ty * 4 + i];
#pragma unroll
            for (int j = 0; j < 4; j++) bb[j] = Bs[kk][tx * 4 + j];
#pragma unroll
            for (int i = 0; i < 4; i++)
#pragma unroll
                for (int j = 0; j < 4; j++) acc[i][j] += a[i] * bb[j];
        }
        __syncthreads();
    }
#pragma unroll
    for (int i = 0; i < 4; i++) {
        int m = bm * 64 + ty * 4 + i;
#pragma unroll
        for (int j = 0; j < 4; j++) {
            int jj = bn * 64 + tx * 4 + j;
            g_P[m * 256 + jj] = acc[i][j] + bx[jj] + bh[jj];
        }
    }
}

// -------- smem layout (float offsets) --------
// Union region:
//   Phase A: wSA fp32 [0, 49152)
//   Phase B: encS half2 words [0, 33280) ; wB fp32 [33280, 53760)
// Small region:
#define OFF_H1   53760   // phase A sHf  / phase B sH   (256)
#define OFF_H2   54016   // phase A sHb  / phase B sC   (256)
#define OFF_RED  54272   // staging (1024)
#define OFF_AL   55296   // alpha (512)
#define OFF_PRE  55808   // pre staging (512)
#define OFF_SM   56320   // softmax scratch (32)
#define SMEM_FLTS 56352  // 225408 bytes

// -------- kernel 3: persistent scan --------
__global__ void __launch_bounds__(NTH, 1) k_scan() {
    extern __shared__ float smem[];
    const int cta = blockIdx.x;
    const int tid = threadIdx.x;
    const int b   = cta >> 1;
    const int jh  = cta & 1;
    const int lane = tid & 31;
    const int w    = tid >> 5;

    float* wSA  = smem;
    __half2* encS2 = (__half2*)smem;
    float* wB   = smem + 33280;
    float* sH1  = smem + OFF_H1;
    float* sH2f = smem + OFF_H2;
    float* sRed = smem + OFF_RED;
    float* sAl  = smem + OFF_AL;
    float* sPre = smem + OFF_PRE;
    float* sSm  = smem + OFF_SM;

    // prologue zeros for exchange buffers (buffer 0 only; 1,2 zeroed by rotation)
    if (tid < 4)   g_e3p[(cta * 4 + tid) * 32] = 0.f;
    if (tid < 128) g_p3[b * 256 + jh * 128 + tid] = 0.f;

    // ---------------- Phase A: fused fwd+bwd scans on jh==0 CTAs ----------------
    if (jh == 0) {
        const int kh  = tid >> 8;
        const int j   = tid & 255;
        const int ks0 = kh ? 96 : 0;
        const int kg0 = kh ? 224 : 192;

        for (int i = tid; i < KS_SMEM * 256; i += NTH) wSA[i] = g_WhT[i];
        if (tid < 256) { sH1[tid] = 0.f; sH2f[tid] = 0.f; }
        __syncthreads();

        float cst = 0.f;
        for (int s = 0; s < Lz; s++) {
            float af = 0.f, ab = 0.f;
            {
                const float4* hf4 = (const float4*)(sH1 + ks0);
                const float4* hb4 = (const float4*)(sH2f + ks0);
                const float* wp = wSA + ks0 * 256 + j;
#pragma unroll 4
                for (int q = 0; q < 24; q++) {
                    float4 hf = hf4[q], hb = hb4[q];
                    const float* w4 = wp + q * 1024;
                    float w0 = w4[0], w1 = w4[256], w2 = w4[512], w3 = w4[768];
                    af += hf.x * w0 + hf.y * w1 + hf.z * w2 + hf.w * w3;
                    ab += hb.x * w0 + hb.y * w1 + hb.z * w2 + hb.w * w3;
                }
            }
            {
                const float4* hf4 = (const float4*)(sH1 + kg0);
                const float4* hb4 = (const float4*)(sH2f + kg0);
                const float* wp = g_WhT + kg0 * 256 + j;
#pragma unroll
                for (int q = 0; q < 8; q++) {
                    float4 hf = hf4[q], hb = hb4[q];
                    const float* w4 = wp + q * 1024;
                    float w0 = w4[0], w1 = w4[256], w2 = w4[512], w3 = w4[768];
                    af += hf.x * w0 + hf.y * w1 + hf.z * w2 + hf.w * w3;
                    ab += hb.x * w0 + hb.y * w1 + hb.z * w2 + hb.w * w3;
                }
            }
            sRed[kh * 256 + j]       = af;
            sRed[512 + kh * 256 + j] = ab;
            __syncthreads();
            if (kh == 0) {
                float pre = sRed[j] + sRed[256 + j] + g_P[((size_t)s * 64 + b) * 256 + j];
                float sg = 1.f / (1.f + expf(-pre));
                float gg = tanhf(pre);
                cst = sg * (cst + gg);
                sH1[j] = sg * tanhf(cst);
            } else {
                float pre = sRed[512 + j] + sRed[768 + j] + g_P[((size_t)(511 - s) * 64 + b) * 256 + j];
                float sg = 1.f / (1.f + expf(-pre));
                float gg = tanhf(pre);
                cst = sg * (cst + gg);
                sH2f[j] = sg * tanhf(cst);
            }
            __syncthreads();
            if (kh == 0)
                g_enc[((size_t)s * 64 + b) * 256 + j] = __float2half(0.5f * (sH1[j] + sH2f[j]));
        }
        __syncthreads();
        if (tid < 256) g_hc[b * 512 + tid] = sH2f[tid];       // h_bwd final
        if (kh == 1)   g_hc[b * 512 + 256 + j] = cst;         // c_bwd final
    }

    gbar();   // phase boundary: enc + hc visible everywhere

    // ---------------- Phase B prologue: load enc half + weights into smem ----------------
    {
        const __half* gsrc = g_enc + (size_t)b * 256 + jh * 128;
#pragma unroll 4
        for (int i = 0; i < 32; i++) {
            int l = w * 32 + i;
            const uint2 v = *(const uint2*)(gsrc + (size_t)l * 16384 + lane * 4);
            unsigned* dst = ((unsigned*)smem) + (l * EPITCH + lane * 2);
            dst[0] = v.x; dst[1] = v.y;
        }
    }
    for (int i = tid; i < WB_ROWS * 256; i += NTH) wB[i] = g_WhT[jh * 128 * 256 + i];
    float cB = 0.f;
    if (tid < 128) {
        sH1[tid] = g_hc[b * 512 + jh * 128 + tid];
        cB       = g_hc[b * 512 + 256 + jh * 128 + tid];
    }
    __syncthreads();

    float* sH = sH1;   // h half (128)
    float* sC = sH2f;  // ctx half (128)

    // ---------------- Phase B: attention scan, 2 grid barriers / step ----------------
    for (int t = 0; t < Lz; t++) {
        const int bufc = t % 3, bufn = (t + 1) % 3;

        // ---- interval 1: energy partial for row l = tid ----
        {
            float e = 0.f;
            const int base = tid * EPITCH;
            const float4* h4 = (const float4*)sH;
#pragma unroll 8
            for (int q2 = 0; q2 < 32; q2++) {
                float4 hv = h4[q2];                                  // h[4q2..4q2+3] (2 jp)
                float2 e0 = __half22float2(encS2[base + q2 * 2]);
                float2 e1 = __half22float2(encS2[base + q2 * 2 + 1]);
                e += e0.x * hv.x + e0.y * hv.y + e1.x * hv.z + e1.y * hv.w;
            }
            atomicAdd(&g_e3p[bufc * 16384 + tid * 32], e);
        }
        gbar();   // barrier E

        // ---- interval 2: softmax (replicated) ----
        float myE = __ldcg(&g_e3p[bufc * 16384 + tid * 32]);
        float m = myE;
#pragma unroll
        for (int o = 16; o > 0; o >>= 1) m = fmaxf(m, __shfl_xor_sync(0xffffffffu, m, o));
        if (lane == 0) sSm[w] = m;
        __syncthreads();
        if (tid == 0) {
            float mm = sSm[0];
#pragma unroll
            for (int ww = 1; ww < 16; ww++) mm = fmaxf(mm, sSm[ww]);
            sSm[16] = mm;
        }
        __syncthreads();
        float M = sSm[16];
        float ex = expf(myE - M);
        float ss = ex;
#pragma unroll
        for (int o = 16; o > 0; o >>= 1) ss += __shfl_xor_sync(0xffffffffu, ss, o);
        if (lane == 0) sSm[w] = ss;
        __syncthreads();
        if (tid == 0) {
            float tot = 0.f;
#pragma unroll
            for (int ww = 0; ww < 16; ww++) tot += sSm[ww];
            sSm[17] = 1.f / tot;
        }
        __syncthreads();
        sAl[tid] = ex * sSm[17];
        if (tid < 4) g_e3p[bufn * 16384 + (cta * 4 + tid) * 32] = 0.f;   // zero next buffer
        __syncthreads();

        // ---- context partial: thread (kp = tid&63, lc = tid>>6) ----
        {
            const int kp = tid & 63, lc = tid >> 6;
            const int l0 = lc * 64;
            float a0 = 0.f, a1 = 0.f;
            const float4* al4 = (const float4*)(sAl + l0);
#pragma unroll 4
            for (int q = 0; q < 16; q++) {
                float4 al = al4[q];
                int l = l0 + q * 4;
                float2 f;
                f = __half22float2(encS2[(l + 0) * EPITCH + kp]); a0 += al.x * f.x; a1 += al.x * f.y;
                f = __half22float2(encS2[(l + 1) * EPITCH + kp]); a0 += al.y * f.x; a1 += al.y * f.y;
                f = __half22float2(encS2[(l + 2) * EPITCH + kp]); a0 += al.z * f.x; a1 += al.z * f.y;
                f = __half22float2(encS2[(l + 3) * EPITCH + kp]); a0 += al.w * f.x; a1 += al.w * f.y;
            }
            sRed[lc * 128 + kp * 2]     = a0;
            sRed[lc * 128 + kp * 2 + 1] = a1;
        }
        __syncthreads();
        if (tid < 128) {
            float cv = sH[tid];
#pragma unroll
            for (int lc = 0; lc < 8; lc++) cv += sRed[lc * 128 + tid];
            sC[tid] = cv;
        }
        __syncthreads();

        // ---- matvec partial: pre_part[j] = sum_{k in my half} ctx[k] W[k][j], all 256 j ----
        {
            const int j = tid & 255, kq = tid >> 8;
            float a = 0.f;
            if (kq == 0) {
                const float4* c4 = (const float4*)sC;
#pragma unroll 4
                for (int q4 = 0; q4 < 16; q4++) {
                    float4 c = c4[q4];
                    const float* w4 = wB + (q4 * 4) * 256 + j;
                    a += c.x * w4[0] + c.y * w4[256] + c.z * w4[512] + c.w * w4[768];
                }
            } else {
                const float4* c4 = (const float4*)(sC + 64);
#pragma unroll
                for (int q4 = 0; q4 < 4; q4++) {                      // k 64..79 smem
                    float4 c = c4[q4];
                    const float* w4 = wB + (64 + q4 * 4) * 256 + j;
                    a += c.x * w4[0] + c.y * w4[256] + c.z * w4[512] + c.w * w4[768];
                }
                const float* gp = g_WhT + (jh * 128) * 256 + j;
#pragma unroll 4
                for (int q4 = 4; q4 < 16; q4++) {                     // k 80..127 L2
                    float4 c = c4[q4];
                    const float* w4 = gp + (64 + q4 * 4) * 256;
                    a += c.x * w4[0] + c.y * w4[256] + c.z * w4[512] + c.w * w4[768];
                }
            }
            sPre[kq * 256 + j] = a;
        }
        __syncthreads();
        if (tid < 256) atomicAdd(&g_p3[bufc * 16384 + b * 256 + tid], sPre[tid] + sPre[256 + tid]);
        gbar();   // barrier P

        // ---- interval 3: cell update on own j-half ----
        if (tid < 128) {
            int gj = jh * 128 + tid;
            float pre = __ldcg(&g_p3[bufc * 16384 + b * 256 + gj])
                      + g_P[((size_t)t * 64 + b) * 256 + gj];
            float sg = 1.f / (1.f + expf(-pre));
            float gg = tanhf(pre);
            cB = sg * (cB + gg);
            float hn = sg * tanhf(cB);
            sH[tid] = hn;
            g_P[((size_t)t * 64 + b) * 256 + gj] = hn;                // listH
            g_p3[bufn * 16384 + b * 256 + gj] = 0.f;                  // zero next buffer (own slice)
        }
        __syncthreads();
    }
}

// -------- kernel 4: out = listH@Wl^T + bl, mask --------
__global__ void k_proj(const float* __restrict__ Wl, const float* __restrict__ bl,
                       const int* __restrict__ slen, float* __restrict__ out) {
    int warp = blockIdx.x * (blockDim.x >> 5) + (threadIdx.x >> 5);
    int lane = threadIdx.x & 31;
    if (warp >= Bz * Lz) return;
    int b = warp >> 9, l = warp & 511;
    const float* hrow = g_P + ((size_t)l * 64 + b) * 256;
    float a0 = 0.f, a1 = 0.f;
#pragma unroll
    for (int i = 0; i < 8; i++) {
        float h = hrow[lane + 32 * i];
        a0 += h * Wl[lane + 32 * i];
        a1 += h * Wl[256 + lane + 32 * i];
    }
    for (int o = 16; o > 0; o >>= 1) {
        a0 += __shfl_down_sync(0xffffffffu, a0, o);
        a1 += __shfl_down_sync(0xffffffffu, a1, o);
    }
    if (lane == 0) {
        float o0 = a0 + bl[0];
        float o1 = a1 + bl[1];
        if (l > slen[b]) { o0 = 0.f; o1 = 1.f; }
        out[(size_t)warp * 2]     = o0;
        out[(size_t)warp * 2 + 1] = o1;
    }
}

// -------- host launcher --------
extern "C" void kernel_launch(void* const* d_in, const int* in_sizes, int n_in,
                              void* d_out, int out_size) {
    const float* x    = (const float*)d_in[0];
    const int*   slen = (const int*)  d_in[1];
    const float* Wh   = (const float*)d_in[2];
    const float* bh   = (const float*)d_in[3];
    const float* Wx   = (const float*)d_in[4];
    const float* bx   = (const float*)d_in[5];
    const float* Wl   = (const float*)d_in[6];
    const float* bl   = (const float*)d_in[7];
    float* out = (float*)d_out;

    const int smem_bytes = SMEM_FLTS * 4;
    cudaFuncSetAttribute(k_scan, cudaFuncAttributeMaxDynamicSharedMemorySize, smem_bytes);

    k_pre<<<256, 256>>>(Wh);
    k_gemm<<<dim3(4, 512), 256>>>(x, Wx, bx, bh);
    k_scan<<<GRID, NTH, smem_bytes>>>();
    k_proj<<<4096, 256>>>(Wl, bl, slen, out);
}